// round 7
// baseline (speedup 1.0000x reference)
#include <cuda_runtime.h>
#include <cuda_bf16.h>
#include <cstdint>

#define DD     1024
#define NSYM   32
#define FF     1024
#define HALF_F 512
#define GRP    64        // CTAs per direction
#define NTHR   256
#define COLS_PER_CTA 16
#define ROWS_PER_CTA 16
#define SV_PAD(j) ((j) + ((j) >> 5))   // +1 float pad per 32 floats

__device__ __nv_bfloat16 g_core_bf[(size_t)NSYM * DD * DD];  // 64 MB, L2-resident
__device__ float g_v[2][DD];
__device__ float g_u[2][DD];

// Paired flags: slot j holds {flag[CTA j] (x), flag[CTA j+32] (y)} -> one 8B
// relaxed vector load per lane checks two CTAs; warp 0 covers all 64.
__device__ int2 g_pack_f[32];
__device__ int2 g_pack_b[32];

// ---------------------------------------------------------------------------
__device__ __forceinline__ int2 ld_relaxed_v2(const int2* p) {
    int2 v;
    asm volatile("ld.relaxed.gpu.v2.b32 {%0,%1}, [%2];"
                 : "=r"(v.x), "=r"(v.y) : "l"(p) : "memory");
    return v;
}
__device__ __forceinline__ void st_release(int* p, int v) {
    asm volatile("st.release.gpu.b32 [%0], %1;" :: "l"(p), "r"(v) : "memory");
}
__device__ __forceinline__ void fence_acqrel_gpu() {
    asm volatile("fence.acq_rel.gpu;" ::: "memory");
}

// ---------------------------------------------------------------------------
// fp32 -> bf16 conversion of the 32 core matrices (192 MB traffic, ~31us)
// ---------------------------------------------------------------------------
__global__ void convert_core_kernel(const float* __restrict__ core) {
    size_t i = ((size_t)blockIdx.x * NTHR + threadIdx.x) * 4;
    float4 f = *reinterpret_cast<const float4*>(core + i);
    __nv_bfloat162 lo = __floats2bfloat162_rn(f.x, f.y);
    __nv_bfloat162 hi = __floats2bfloat162_rn(f.z, f.w);
    uint2 o;
    o.x = *reinterpret_cast<unsigned*>(&lo);
    o.y = *reinterpret_cast<unsigned*>(&hi);
    *reinterpret_cast<uint2*>(g_core_bf + i) = o;
}

// ---------------------------------------------------------------------------
__global__ void init_kernel(const float* __restrict__ left,
                            const float* __restrict__ right) {
    int t = threadIdx.x;
    if (t < DD) {
        g_v[0][t] = left[t];
        g_u[0][t] = right[t];
    }
    if (t < 32) {
        g_pack_f[t] = make_int2(0, 0);
        g_pack_b[t] = make_int2(0, 0);
    }
}

// ---------------------------------------------------------------------------
// Persistent chain: blocks 0..63 forward (v <- v M), 64..127 backward (u <- M u).
// Matrix prefetch issued BEFORE the poll (completes during the barrier wait).
// Barrier: paired-flag relaxed poll (1 load/lane/round) + acquire fence;
// producers publish with a release store (no stalling fence).
// ---------------------------------------------------------------------------
__global__ __launch_bounds__(NTHR, 1)
void chain_kernel(const int* __restrict__ x, float* __restrict__ out) {
    __shared__ int   sx[HALF_F];
    __shared__ float svec[DD + DD / 32];
    __shared__ float red[8][16];

    const int tid = threadIdx.x;
    const bool is_fwd = (blockIdx.x < GRP);

    if (is_fwd) {
        // ============================ FORWARD ==============================
        const int b  = blockIdx.x;
        const int jb = b * COLS_PER_CTA;
        int* myflag = &(reinterpret_cast<int*>(g_pack_f))[2 * (b & 31) + (b >> 5)];

        for (int i = tid; i < HALF_F; i += NTHR) sx[i] = x[i];
        __syncthreads();

        const int q = tid & 3;    // column quad
        const int g = tid >> 2;   // row group 0..63; rows g + 64*i

        for (int s = 0; s < HALF_F; ++s) {
            const int sym = sx[s];
            // ---- prefetch matrix slice (pipelines under the barrier wait)
            const uint2* mp = reinterpret_cast<const uint2*>(
                g_core_bf + (size_t)sym * DD * DD + (size_t)g * DD + jb + 4 * q);
            uint2 pre[16];
#pragma unroll
            for (int i = 0; i < 16; ++i)
                pre[i] = __ldg(mp + (size_t)i * (64 * DD / 4));

            // ---- barrier: all fwd CTAs finished step s-1 (1 load/lane/round)
            if (tid < 32) {
                const int2* fp = &g_pack_f[tid];
                int2 t;
                do { t = ld_relaxed_v2(fp); }
                while (!__all_sync(0xffffffffu, t.x >= s && t.y >= s));
                fence_acqrel_gpu();
            }
            __syncthreads();

            // ---- stage FULL v (1024 floats) into smem
            const float* vcur = g_v[s & 1];
            {
                int j0 = 4 * tid;
                float4 t4 = __ldcg(reinterpret_cast<const float4*>(vcur + j0));
                svec[SV_PAD(j0) + 0] = t4.x;
                svec[SV_PAD(j0) + 1] = t4.y;
                svec[SV_PAD(j0) + 2] = t4.z;
                svec[SV_PAD(j0) + 3] = t4.w;
            }
            __syncthreads();

            // ---- accumulate 4 output columns over 16 rows
            float a0 = 0.f, a1 = 0.f, a2 = 0.f, a3 = 0.f;
#pragma unroll
            for (int i = 0; i < 16; ++i) {
                float vv = svec[SV_PAD(g + 64 * i)];
                uint2 m = pre[i];
                a0 += vv * __uint_as_float(m.x << 16);
                a1 += vv * __uint_as_float(m.x & 0xffff0000u);
                a2 += vv * __uint_as_float(m.y << 16);
                a3 += vv * __uint_as_float(m.y & 0xffff0000u);
            }
#pragma unroll
            for (int off = 16; off >= 4; off >>= 1) {
                a0 += __shfl_down_sync(0xffffffffu, a0, off);
                a1 += __shfl_down_sync(0xffffffffu, a1, off);
                a2 += __shfl_down_sync(0xffffffffu, a2, off);
                a3 += __shfl_down_sync(0xffffffffu, a3, off);
            }
            const int lane = tid & 31, w = tid >> 5;
            if (lane < 4) {
                red[w][lane * 4 + 0] = a0;
                red[w][lane * 4 + 1] = a1;
                red[w][lane * 4 + 2] = a2;
                red[w][lane * 4 + 3] = a3;
            }
            __syncthreads();

            float* vnext = g_v[(s + 1) & 1];
            if (tid < 16) {
                float sum = 0.f;
#pragma unroll
                for (int w2 = 0; w2 < 8; ++w2) sum += red[w2][tid];
                __stcg(&vnext[jb + tid], sum);
            }
            __syncthreads();
            if (tid == 0) st_release(myflag, s + 1);   // release-publish step
        }
    } else {
        // ============================ BACKWARD =============================
        const int c  = blockIdx.x - GRP;
        const int kb = c * ROWS_PER_CTA;
        int* myflag = &(reinterpret_cast<int*>(g_pack_b))[2 * (c & 31) + (c >> 5)];

        for (int i = tid; i < HALF_F; i += NTHR) sx[i] = x[(FF - 1) - i];
        __syncthreads();

        const int r  = tid >> 4;   // row within slice
        const int ch = tid & 15;   // 64-col chunk

        for (int s = 0; s < HALF_F; ++s) {
            const int sym = sx[s];
            const uint4* mp = reinterpret_cast<const uint4*>(
                g_core_bf + (size_t)sym * DD * DD + (size_t)(kb + r) * DD + ch * 64);
            uint4 pre[8];
#pragma unroll
            for (int i = 0; i < 8; ++i) pre[i] = __ldg(mp + i);

            if (tid < 32) {
                const int2* fp = &g_pack_b[tid];
                int2 t;
                do { t = ld_relaxed_v2(fp); }
                while (!__all_sync(0xffffffffu, t.x >= s && t.y >= s));
                fence_acqrel_gpu();
            }
            __syncthreads();

            const float* ucur = g_u[s & 1];
            {
                int j0 = 4 * tid;
                float4 t4 = __ldcg(reinterpret_cast<const float4*>(ucur + j0));
                svec[SV_PAD(j0) + 0] = t4.x;
                svec[SV_PAD(j0) + 1] = t4.y;
                svec[SV_PAD(j0) + 2] = t4.z;
                svec[SV_PAD(j0) + 3] = t4.w;
            }
            __syncthreads();

            float acc = 0.f;
#pragma unroll
            for (int i = 0; i < 8; ++i) {
                const int j0 = ch * 64 + i * 8;
                uint4 m = pre[i];
                acc += svec[SV_PAD(j0 + 0)] * __uint_as_float(m.x << 16);
                acc += svec[SV_PAD(j0 + 1)] * __uint_as_float(m.x & 0xffff0000u);
                acc += svec[SV_PAD(j0 + 2)] * __uint_as_float(m.y << 16);
                acc += svec[SV_PAD(j0 + 3)] * __uint_as_float(m.y & 0xffff0000u);
                acc += svec[SV_PAD(j0 + 4)] * __uint_as_float(m.z << 16);
                acc += svec[SV_PAD(j0 + 5)] * __uint_as_float(m.z & 0xffff0000u);
                acc += svec[SV_PAD(j0 + 6)] * __uint_as_float(m.w << 16);
                acc += svec[SV_PAD(j0 + 7)] * __uint_as_float(m.w & 0xffff0000u);
            }
#pragma unroll
            for (int off = 8; off >= 1; off >>= 1)
                acc += __shfl_down_sync(0xffffffffu, acc, off);

            float* unext = g_u[(s + 1) & 1];
            if ((tid & 15) == 0)
                __stcg(&unext[kb + r], acc);
            __syncthreads();
            if (tid == 0) st_release(myflag, s + 1);
        }
    }

    // ======================== FINAL COMBINE (block 0) ======================
    if (blockIdx.x == 0) {
        if (tid < 32) {
            const int2* f0 = &g_pack_f[tid];
            const int2* f1 = &g_pack_b[tid];
            int2 a, b2;
            do { a = ld_relaxed_v2(f0); b2 = ld_relaxed_v2(f1); }
            while (!__all_sync(0xffffffffu,
                               a.x >= HALF_F && a.y >= HALF_F &&
                               b2.x >= HALF_F && b2.y >= HALF_F));
            fence_acqrel_gpu();
        }
        __syncthreads();

        float p = 0.f;
        for (int i = tid; i < DD; i += NTHR)
            p += __ldcg(&g_v[0][i]) * __ldcg(&g_u[0][i]);
#pragma unroll
        for (int off = 16; off >= 1; off >>= 1)
            p += __shfl_down_sync(0xffffffffu, p, off);

        __shared__ float fin[8];
        if ((tid & 31) == 0) fin[tid >> 5] = p;
        __syncthreads();
        if (tid == 0) {
            float t = 0.f;
#pragma unroll
            for (int w2 = 0; w2 < 8; ++w2) t += fin[w2];
            out[0] = t;
        }
    }
}

// ---------------------------------------------------------------------------
extern "C" void kernel_launch(void* const* d_in, const int* in_sizes, int n_in,
                              void* d_out, int out_size) {
    const int*   x     = (const int*)d_in[0];
    const float* core  = (const float*)d_in[1];
    const float* left  = (const float*)d_in[2];
    const float* right = (const float*)d_in[3];
    float* out = (float*)d_out;

    convert_core_kernel<<<32768, NTHR>>>(core);
    init_kernel<<<1, 1024>>>(left, right);
    chain_kernel<<<2 * GRP, NTHR>>>(x, out);
}

// round 11
// speedup vs baseline: 1.3385x; 1.3385x over previous
#include <cuda_runtime.h>
#include <cuda_bf16.h>
#include <cstdint>

#define DD     1024
#define NSYM   32
#define FF     1024
#define HALF_F 512
#define GRP    64        // CTAs per direction
#define NTHR   256
#define COLS_PER_CTA 16
#define ROWS_PER_CTA 16
#define SV_PAD(j) ((j) + ((j) >> 5))   // +1 float pad per 32 floats

__device__ __nv_bfloat16 g_core_bf[(size_t)NSYM * DD * DD];  // 64 MB, L2-resident
__device__ float g_v[2][DD];
__device__ float g_u[2][DD];

// 128B-isolated per-CTA flags: spreads barrier traffic across LTS slices.
struct Flag { int v; int pad[31]; };
__device__ Flag g_flag_f[GRP];
__device__ Flag g_flag_b[GRP];

// ---------------------------------------------------------------------------
__device__ __forceinline__ int ld_acquire(const int* p) {
    int v;
    asm volatile("ld.acquire.gpu.b32 %0, [%1];" : "=r"(v) : "l"(p) : "memory");
    return v;
}
__device__ __forceinline__ void st_relaxed(int* p, int v) {
    asm volatile("st.relaxed.gpu.b32 [%0], %1;" :: "l"(p), "r"(v) : "memory");
}
__device__ __forceinline__ void fence_acqrel_gpu() {
    asm volatile("fence.acq_rel.gpu;" ::: "memory");
}

// ---------------------------------------------------------------------------
// fp32 -> bf16 conversion of the 32 core matrices (192 MB traffic, ~31us)
// ---------------------------------------------------------------------------
__global__ void convert_core_kernel(const float* __restrict__ core) {
    size_t i = ((size_t)blockIdx.x * NTHR + threadIdx.x) * 4;
    float4 f = *reinterpret_cast<const float4*>(core + i);
    __nv_bfloat162 lo = __floats2bfloat162_rn(f.x, f.y);
    __nv_bfloat162 hi = __floats2bfloat162_rn(f.z, f.w);
    uint2 o;
    o.x = *reinterpret_cast<unsigned*>(&lo);
    o.y = *reinterpret_cast<unsigned*>(&hi);
    *reinterpret_cast<uint2*>(g_core_bf + i) = o;
}

// ---------------------------------------------------------------------------
__global__ void init_kernel(const float* __restrict__ left,
                            const float* __restrict__ right) {
    int t = threadIdx.x;
    if (t < DD) {
        g_v[0][t] = left[t];
        g_u[0][t] = right[t];
    }
    if (t < GRP) {
        g_flag_f[t].v = 0;
        g_flag_b[t].v = 0;
    }
}

// ---------------------------------------------------------------------------
// Persistent chain: blocks 0..63 forward (v <- v M), 64..127 backward (u <- M u).
// Matrix prefetch issued BEFORE the poll (completes during the barrier wait).
// Barrier: 64 lanes (warps 0-1), ONE flag per lane, each lane spins on its own
// 128B-isolated flag (parallel across LTS slices, 1 L2 roundtrip per round).
// ---------------------------------------------------------------------------
__global__ __launch_bounds__(NTHR, 1)
void chain_kernel(const int* __restrict__ x, float* __restrict__ out) {
    __shared__ int   sx[HALF_F];
    __shared__ float svec[DD + DD / 32];
    __shared__ float red[8][16];

    const int tid = threadIdx.x;
    const bool is_fwd = (blockIdx.x < GRP);

    if (is_fwd) {
        // ============================ FORWARD ==============================
        const int b  = blockIdx.x;
        const int jb = b * COLS_PER_CTA;

        for (int i = tid; i < HALF_F; i += NTHR) sx[i] = x[i];
        __syncthreads();

        const int q = tid & 3;    // column quad
        const int g = tid >> 2;   // row group 0..63; rows g + 64*i

        for (int s = 0; s < HALF_F; ++s) {
            const int sym = sx[s];
            // ---- prefetch matrix slice (pipelines under the barrier wait)
            const uint2* mp = reinterpret_cast<const uint2*>(
                g_core_bf + (size_t)sym * DD * DD + (size_t)g * DD + jb + 4 * q);
            uint2 pre[16];
#pragma unroll
            for (int i = 0; i < 16; ++i)
                pre[i] = __ldg(mp + (size_t)i * (64 * DD / 4));

            // ---- barrier: one flag per lane, spin until own flag reaches s
            if (tid < GRP) {
                const int* f = &g_flag_f[tid].v;
                while (ld_acquire(f) < s) { }
            }
            __syncthreads();

            // ---- stage FULL v (1024 floats) into smem
            const float* vcur = g_v[s & 1];
            {
                int j0 = 4 * tid;
                float4 t4 = __ldcg(reinterpret_cast<const float4*>(vcur + j0));
                svec[SV_PAD(j0) + 0] = t4.x;
                svec[SV_PAD(j0) + 1] = t4.y;
                svec[SV_PAD(j0) + 2] = t4.z;
                svec[SV_PAD(j0) + 3] = t4.w;
            }
            __syncthreads();

            // ---- accumulate 4 output columns over 16 rows
            float a0 = 0.f, a1 = 0.f, a2 = 0.f, a3 = 0.f;
#pragma unroll
            for (int i = 0; i < 16; ++i) {
                float vv = svec[SV_PAD(g + 64 * i)];
                uint2 m = pre[i];
                a0 += vv * __uint_as_float(m.x << 16);
                a1 += vv * __uint_as_float(m.x & 0xffff0000u);
                a2 += vv * __uint_as_float(m.y << 16);
                a3 += vv * __uint_as_float(m.y & 0xffff0000u);
            }
#pragma unroll
            for (int off = 16; off >= 4; off >>= 1) {
                a0 += __shfl_down_sync(0xffffffffu, a0, off);
                a1 += __shfl_down_sync(0xffffffffu, a1, off);
                a2 += __shfl_down_sync(0xffffffffu, a2, off);
                a3 += __shfl_down_sync(0xffffffffu, a3, off);
            }
            const int lane = tid & 31, w = tid >> 5;
            if (lane < 4) {
                red[w][lane * 4 + 0] = a0;
                red[w][lane * 4 + 1] = a1;
                red[w][lane * 4 + 2] = a2;
                red[w][lane * 4 + 3] = a3;
            }
            __syncthreads();

            // ---- writers (tid<16) are all in warp 0: syncwarp + publish
            if (tid < 32) {
                if (tid < 16) {
                    float sum = 0.f;
#pragma unroll
                    for (int w2 = 0; w2 < 8; ++w2) sum += red[w2][tid];
                    __stcg(&g_v[(s + 1) & 1][jb + tid], sum);
                }
                __syncwarp();
                if (tid == 0) {
                    fence_acqrel_gpu();                 // release our v writes
                    st_relaxed(&g_flag_f[b].v, s + 1);  // announce step done
                }
            }
        }
    } else {
        // ============================ BACKWARD =============================
        const int c  = blockIdx.x - GRP;
        const int kb = c * ROWS_PER_CTA;

        for (int i = tid; i < HALF_F; i += NTHR) sx[i] = x[(FF - 1) - i];
        __syncthreads();

        const int r  = tid >> 4;   // row within slice
        const int ch = tid & 15;   // 64-col chunk

        for (int s = 0; s < HALF_F; ++s) {
            const int sym = sx[s];
            const uint4* mp = reinterpret_cast<const uint4*>(
                g_core_bf + (size_t)sym * DD * DD + (size_t)(kb + r) * DD + ch * 64);
            uint4 pre[8];
#pragma unroll
            for (int i = 0; i < 8; ++i) pre[i] = __ldg(mp + i);

            if (tid < GRP) {
                const int* f = &g_flag_b[tid].v;
                while (ld_acquire(f) < s) { }
            }
            __syncthreads();

            const float* ucur = g_u[s & 1];
            {
                int j0 = 4 * tid;
                float4 t4 = __ldcg(reinterpret_cast<const float4*>(ucur + j0));
                svec[SV_PAD(j0) + 0] = t4.x;
                svec[SV_PAD(j0) + 1] = t4.y;
                svec[SV_PAD(j0) + 2] = t4.z;
                svec[SV_PAD(j0) + 3] = t4.w;
            }
            __syncthreads();

            float acc = 0.f;
#pragma unroll
            for (int i = 0; i < 8; ++i) {
                const int j0 = ch * 64 + i * 8;
                uint4 m = pre[i];
                acc += svec[SV_PAD(j0 + 0)] * __uint_as_float(m.x << 16);
                acc += svec[SV_PAD(j0 + 1)] * __uint_as_float(m.x & 0xffff0000u);
                acc += svec[SV_PAD(j0 + 2)] * __uint_as_float(m.y << 16);
                acc += svec[SV_PAD(j0 + 3)] * __uint_as_float(m.y & 0xffff0000u);
                acc += svec[SV_PAD(j0 + 4)] * __uint_as_float(m.z << 16);
                acc += svec[SV_PAD(j0 + 5)] * __uint_as_float(m.z & 0xffff0000u);
                acc += svec[SV_PAD(j0 + 6)] * __uint_as_float(m.w << 16);
                acc += svec[SV_PAD(j0 + 7)] * __uint_as_float(m.w & 0xffff0000u);
            }
#pragma unroll
            for (int off = 8; off >= 1; off >>= 1)
                acc += __shfl_down_sync(0xffffffffu, acc, off);

            if ((tid & 15) == 0)
                __stcg(&g_u[(s + 1) & 1][kb + r], acc);
            __syncthreads();
            if (tid == 0) {
                fence_acqrel_gpu();
                st_relaxed(&g_flag_b[c].v, s + 1);
            }
        }
    }

    // ======================== FINAL COMBINE (block 0) ======================
    if (blockIdx.x == 0) {
        if (tid < 128) {
            const int* f = (tid < 64) ? &g_flag_f[tid].v : &g_flag_b[tid - 64].v;
            while (ld_acquire(f) < HALF_F) { }
        }
        __syncthreads();

        float p = 0.f;
        for (int i = tid; i < DD; i += NTHR)
            p += __ldcg(&g_v[0][i]) * __ldcg(&g_u[0][i]);
#pragma unroll
        for (int off = 16; off >= 1; off >>= 1)
            p += __shfl_down_sync(0xffffffffu, p, off);

        __shared__ float fin[8];
        if ((tid & 31) == 0) fin[tid >> 5] = p;
        __syncthreads();
        if (tid == 0) {
            float t = 0.f;
#pragma unroll
            for (int w2 = 0; w2 < 8; ++w2) t += fin[w2];
            out[0] = t;
        }
    }
}

// ---------------------------------------------------------------------------
extern "C" void kernel_launch(void* const* d_in, const int* in_sizes, int n_in,
                              void* d_out, int out_size) {
    const int*   x     = (const int*)d_in[0];
    const float* core  = (const float*)d_in[1];
    const float* left  = (const float*)d_in[2];
    const float* right = (const float*)d_in[3];
    float* out = (float*)d_out;

    convert_core_kernel<<<32768, NTHR>>>(core);
    init_kernel<<<1, 1024>>>(left, right);
    chain_kernel<<<2 * GRP, NTHR>>>(x, out);
}